// round 17
// baseline (speedup 1.0000x reference)
#include <cuda_runtime.h>
#include <cuda_bf16.h>
#include <cstdint>

#define Dm   192
#define DIN  384
#define NSz  16
#define DTRz 12
#define KC   4
#define CIN  96
#define Bz   2
#define L0z  3136
#define L1z  784
#define BL0  (Bz*L0z)
#define NCHMAX 49
#define ASTR 40   // smem row stride in bf16 elements (conflict-free)

// ---------------- static scratch (no allocs allowed) ----------------
__device__ float g_x   [Bz*L0z*Dm];      // activation (B, L, D)
__device__ float g_h   [BL0*Dm];         // xT for stem, then layernorm output (B*L, D)
__device__ float g_xz  [BL0*2*DIN];
__device__ float g_xi  [BL0*DIN];
__device__ float g_proj[BL0*44];
__device__ float g_dt  [BL0*DIN];
__device__ float g_y   [BL0*DIN];
__device__ float g_blk [BL0*Dm];
__device__ float g_Pc  [Bz*NCHMAX*DIN*NSz];
__device__ float g_Hc  [Bz*NCHMAX*DIN*NSz];
__device__ float g_w2  [Dm*CIN];         // BN-folded stem weight
__device__ float g_b2  [Dm];             // BN-folded stem bias

#define MMA_BF16(c, a, b)                                                     \
    asm volatile("mma.sync.aligned.m16n8k16.row.col.f32.bf16.bf16.f32 "       \
        "{%0,%1,%2,%3},{%4,%5,%6,%7},{%8,%9},{%0,%1,%2,%3};"                  \
        : "+f"((c)[0]), "+f"((c)[1]), "+f"((c)[2]), "+f"((c)[3])              \
        : "r"((a)[0]), "r"((a)[1]), "r"((a)[2]), "r"((a)[3]),                 \
          "r"((b)[0]), "r"((b)[1]))

__device__ __forceinline__ uint32_t pack2(__nv_bfloat16 a, __nv_bfloat16 b) {
    return (uint32_t)__bfloat16_as_ushort(a) | ((uint32_t)__bfloat16_as_ushort(b) << 16);
}
__device__ __forceinline__ void split2(float x, float y, uint32_t& hi, uint32_t& lo) {
    __nv_bfloat16 hx = __float2bfloat16(x), hy = __float2bfloat16(y);
    __nv_bfloat16 lx = __float2bfloat16(x - __bfloat162float(hx));
    __nv_bfloat16 ly = __float2bfloat16(y - __bfloat162float(hy));
    hi = pack2(hx, hy);
    lo = pack2(lx, ly);
}

// ============ bf16x3 tensor-core GEMM: C = A(M,K)*B(N,K)^T + bias ============
// (proven R12/R15 kernel, untouched)
template<int BN>
__global__ __launch_bounds__(256) void bgemm(
        const float* __restrict__ A, int lda,
        const float* __restrict__ B, int ldb,
        const float* __restrict__ bias,
        float* __restrict__ C, int ldc,
        int M, int N, int K, int act, int addC) {
    constexpr int J = BN / 32;
    __shared__ __align__(16) uint16_t sAh[128*ASTR];
    __shared__ __align__(16) uint16_t sAl[128*ASTR];
    __shared__ __align__(16) uint16_t sBh[BN*ASTR];
    __shared__ __align__(16) uint16_t sBl[BN*ASTR];

    int bm = blockIdx.y * 128, bn = blockIdx.x * BN;
    int tid  = threadIdx.x;
    int lane = tid & 31;
    int w    = tid >> 5;
    int m0 = (w & 1) * 64;
    int n0 = (w >> 1) * (BN/4);
    int gq = lane >> 2;
    int tq = lane & 3;

    float c[4][J][4];
    #pragma unroll
    for (int i = 0; i < 4; i++)
        #pragma unroll
        for (int j = 0; j < J; j++)
            #pragma unroll
            for (int t = 0; t < 4; t++) c[i][j][t] = 0.f;

    float4 pa[4], pb[J];
    const float4 z4 = make_float4(0.f,0.f,0.f,0.f);

    auto ldA = [&](int k0) {
        #pragma unroll
        for (int it = 0; it < 4; it++) {
            int idx = tid + it*256;
            int r = idx >> 3, q = idx & 7;
            int gm = bm + r, gk = k0 + q*4;
            pa[it] = (gm < M && gk < K) ? *(const float4*)(A + (size_t)gm*lda + gk) : z4;
        }
    };
    auto ldB = [&](int k0) {
        #pragma unroll
        for (int it = 0; it < J; it++) {
            int idx = tid + it*256;
            int r = idx >> 3, q = idx & 7;
            int gn = bn + r, gk = k0 + q*4;
            pb[it] = (gn < N && gk < K) ? *(const float4*)(B + (size_t)gn*ldb + gk) : z4;
        }
    };
    auto stA = [&]() {
        #pragma unroll
        for (int it = 0; it < 4; it++) {
            int idx = tid + it*256;
            int r = idx >> 3, q = idx & 7;
            uint32_t h0, l0, h1, l1;
            split2(pa[it].x, pa[it].y, h0, l0);
            split2(pa[it].z, pa[it].w, h1, l1);
            int off = r*ASTR + q*4;
            *(uint2*)(sAh + off) = make_uint2(h0, h1);
            *(uint2*)(sAl + off) = make_uint2(l0, l1);
        }
    };
    auto stB = [&]() {
        #pragma unroll
        for (int it = 0; it < J; it++) {
            int idx = tid + it*256;
            int r = idx >> 3, q = idx & 7;
            uint32_t h0, l0, h1, l1;
            split2(pb[it].x, pb[it].y, h0, l0);
            split2(pb[it].z, pb[it].w, h1, l1);
            int off = r*ASTR + q*4;
            *(uint2*)(sBh + off) = make_uint2(h0, h1);
            *(uint2*)(sBl + off) = make_uint2(l0, l1);
        }
    };

    int nst = (K + 31) / 32;
    ldA(0); ldB(0);
    for (int s = 0; s < nst; s++) {
        stA(); stB();
        __syncthreads();
        if (s + 1 < nst) { ldA((s+1)*32); ldB((s+1)*32); }

        #pragma unroll
        for (int ks = 0; ks < 32; ks += 16) {
            uint32_t ah[4][4], al[4][4], bh[J][2], bl[J][2];
            #pragma unroll
            for (int i = 0; i < 4; i++) {
                int mb = m0 + i*16 + gq;
                int o0 = mb*ASTR + 2*tq + ks;
                int o1 = (mb+8)*ASTR + 2*tq + ks;
                ah[i][0] = *(const uint32_t*)(sAh + o0);
                ah[i][1] = *(const uint32_t*)(sAh + o1);
                ah[i][2] = *(const uint32_t*)(sAh + o0 + 8);
                ah[i][3] = *(const uint32_t*)(sAh + o1 + 8);
                al[i][0] = *(const uint32_t*)(sAl + o0);
                al[i][1] = *(const uint32_t*)(sAl + o1);
                al[i][2] = *(const uint32_t*)(sAl + o0 + 8);
                al[i][3] = *(const uint32_t*)(sAl + o1 + 8);
            }
            #pragma unroll
            for (int j = 0; j < J; j++) {
                int nb = n0 + j*8 + gq;
                int o = nb*ASTR + 2*tq + ks;
                bh[j][0] = *(const uint32_t*)(sBh + o);
                bh[j][1] = *(const uint32_t*)(sBh + o + 8);
                bl[j][0] = *(const uint32_t*)(sBl + o);
                bl[j][1] = *(const uint32_t*)(sBl + o + 8);
            }
            #pragma unroll
            for (int i = 0; i < 4; i++)
                #pragma unroll
                for (int j = 0; j < J; j++) {
                    MMA_BF16(c[i][j], ah[i], bh[j]);
                    MMA_BF16(c[i][j], al[i], bh[j]);
                    MMA_BF16(c[i][j], ah[i], bl[j]);
                }
        }
        __syncthreads();
    }

    #pragma unroll
    for (int i = 0; i < 4; i++) {
        #pragma unroll
        for (int j = 0; j < J; j++) {
            int n = bn + n0 + j*8 + tq*2;
            if (n >= N) continue;
            float b0 = bias ? bias[n]   : 0.f;
            float b1 = bias ? bias[n+1] : 0.f;
            #pragma unroll
            for (int hh = 0; hh < 2; hh++) {
                int gm = bm + m0 + i*16 + gq + hh*8;
                if (gm >= M) continue;
                float v0 = c[i][j][hh*2 + 0] + b0;
                float v1 = c[i][j][hh*2 + 1] + b1;
                float* cp = C + (size_t)gm*ldc + n;
                if (addC) {
                    float2 old = *(float2*)cp;
                    v0 += old.x; v1 += old.y;
                } else if (act == 1) {
                    v0 = (v0 > 20.f) ? v0 : log1pf(__expf(v0));
                    v1 = (v1 > 20.f) ? v1 : log1pf(__expf(v1));
                }
                *(float2*)cp = make_float2(v0, v1);
            }
        }
    }
}

// ------- fused stem prep: transpose x (B,96,L0)->(B,L0,96) AND BN-fold ------
// blocks [0, 588): transpose tiles; blocks [588, 660): weight fold
__global__ void stem_prep(const float* __restrict__ src, float* __restrict__ dst,
                          const float* __restrict__ w, const float* __restrict__ pb,
                          const float* __restrict__ bg, const float* __restrict__ bb,
                          const float* __restrict__ bm, const float* __restrict__ bv,
                          float* __restrict__ w2, float* __restrict__ b2) {
    int bi = blockIdx.x;
    if (bi < 588) {
        __shared__ float s[32][33];
        int b  = bi / 294;
        int rest = bi % 294;
        int d0 = (rest / 98) * 32;
        int l0 = (rest % 98) * 32;
        int tx = threadIdx.x & 31, ty = threadIdx.x >> 5;
        #pragma unroll
        for (int i = 0; i < 32; i += 8) {
            int d = d0 + ty + i, l = l0 + tx;
            s[ty+i][tx] = src[((size_t)b*CIN + d)*L0z + l];
        }
        __syncthreads();
        #pragma unroll
        for (int i = 0; i < 32; i += 8) {
            int l = l0 + ty + i, d = d0 + tx;
            dst[((size_t)b*L0z + l)*CIN + d] = s[tx][ty+i];
        }
    } else {
        int idx = (bi - 588)*256 + threadIdx.x;
        if (idx >= Dm*CIN) return;
        int o = idx / CIN, c = idx % CIN;
        float sc = rsqrtf(bv[o] + 1e-5f) * bg[o];
        w2[idx] = w[idx] * sc;
        if (c == 0) b2[o] = bb[o] - bm[o]*sc + pb[o]*sc;
    }
}

// ---------------- transpose (B,L,Dm)->(B,Dm,L) (for outputs) ----------------
__global__ void transpose_ld(const float* __restrict__ src, float* __restrict__ dst,
                             int L) {
    __shared__ float s[32][33];
    int b  = blockIdx.z;
    int d0 = blockIdx.y * 32;
    int l0 = blockIdx.x * 32;
    int tx = threadIdx.x, ty = threadIdx.y;
    #pragma unroll
    for (int i = 0; i < 32; i += 8) {
        int l = l0 + ty + i, d = d0 + tx;
        if (l < L) s[ty+i][tx] = src[((size_t)b*L + l)*Dm + d];
    }
    __syncthreads();
    #pragma unroll
    for (int i = 0; i < 32; i += 8) {
        int d = d0 + ty + i, l = l0 + tx;
        if (l < L) dst[((size_t)b*Dm + d)*L + l] = s[tx][ty+i];
    }
}

// ---------------- row LayerNorm over D=192 (float2 vectorized) ----------------
__global__ void ln_row(const float* __restrict__ xin, const float* __restrict__ g,
                       const float* __restrict__ bb, float* __restrict__ hout) {
    int warp = threadIdx.x >> 5, lane = threadIdx.x & 31;
    int row = blockIdx.x*8 + warp;
    const float2* xr = (const float2*)(xin + (size_t)row*Dm);
    float2 v[3]; float sum = 0.f, sq = 0.f;
    #pragma unroll
    for (int j = 0; j < 3; j++) {
        v[j] = xr[lane + 32*j];
        sum += v[j].x + v[j].y;
        sq  += v[j].x*v[j].x + v[j].y*v[j].y;
    }
    #pragma unroll
    for (int o = 16; o > 0; o >>= 1) {
        sum += __shfl_xor_sync(0xffffffffu, sum, o);
        sq  += __shfl_xor_sync(0xffffffffu, sq,  o);
    }
    float mu = sum * (1.f/Dm);
    float var = sq * (1.f/Dm) - mu*mu;
    float rs = rsqrtf(var + 1e-5f);
    float2* orow = (float2*)(hout + (size_t)row*Dm);
    const float2* g2 = (const float2*)g;
    const float2* b2p = (const float2*)bb;
    #pragma unroll
    for (int j = 0; j < 3; j++) {
        int c2 = lane + 32*j;
        float2 gv = g2[c2], bv = b2p[c2];
        orow[c2] = make_float2((v[j].x-mu)*rs*gv.x + bv.x,
                               (v[j].y-mu)*rs*gv.y + bv.y);
    }
}

// -------- fused 2x2 maxpool + row LayerNorm (float2) -----
__global__ void ln_pool(const float* __restrict__ xin, const float* __restrict__ g,
                        const float* __restrict__ bb, float* __restrict__ hout) {
    int warp = threadIdx.x >> 5, lane = threadIdx.x & 31;
    int row = blockIdx.x*8 + warp;          // 0 .. Bz*L1z-1
    int b = row / L1z;
    int l = row % L1z;
    int ho = l / 28, wo = l % 28;
    const float2* p0 = (const float2*)(xin + ((size_t)b*L0z + (2*ho)*56 + 2*wo)*Dm);
    const int S = Dm/2;   // float2 row stride
    float2 v[3]; float sum = 0.f, sq = 0.f;
    #pragma unroll
    for (int j = 0; j < 3; j++) {
        int c2 = lane + 32*j;
        float2 a0 = p0[c2],        a1 = p0[S + c2];
        float2 a2 = p0[56*S + c2], a3 = p0[57*S + c2];
        float2 vv = make_float2(fmaxf(fmaxf(a0.x,a1.x), fmaxf(a2.x,a3.x)),
                                fmaxf(fmaxf(a0.y,a1.y), fmaxf(a2.y,a3.y)));
        v[j] = vv;
        sum += vv.x + vv.y;
        sq  += vv.x*vv.x + vv.y*vv.y;
    }
    #pragma unroll
    for (int o = 16; o > 0; o >>= 1) {
        sum += __shfl_xor_sync(0xffffffffu, sum, o);
        sq  += __shfl_xor_sync(0xffffffffu, sq,  o);
    }
    float mu = sum * (1.f/Dm);
    float var = sq * (1.f/Dm) - mu*mu;
    float rs = rsqrtf(var + 1e-5f);
    float2* orow = (float2*)(hout + (size_t)row*Dm);
    const float2* g2 = (const float2*)g;
    const float2* b2p = (const float2*)bb;
    #pragma unroll
    for (int j = 0; j < 3; j++) {
        int c2 = lane + 32*j;
        float2 gv = g2[c2], bv = b2p[c2];
        orow[c2] = make_float2((v[j].x-mu)*rs*gv.x + bv.x,
                               (v[j].y-mu)*rs*gv.y + bv.y);
    }
}

// ---------------- causal depthwise conv (K=4) + SiLU, float4 staging --------
__global__ __launch_bounds__(384) void conv_silu2(const float* __restrict__ xz,
                                                  const float* __restrict__ w,
                                                  const float* __restrict__ cb,
                                                  float* __restrict__ xo, int L) {
    __shared__ __align__(16) float sx[19*384];
    int ntile = L / 16;
    int b  = blockIdx.x / ntile;
    int l0 = (blockIdx.x % ntile) * 16;
    const float4 z4 = make_float4(0.f,0.f,0.f,0.f);
    for (int idx4 = threadIdx.x; idx4 < 19*96; idx4 += 384) {
        int r = idx4 / 96, e4 = idx4 % 96;
        int l = l0 - 3 + r;
        float4 val = (l >= 0) ? *(const float4*)(xz + ((size_t)b*L + l)*(2*DIN) + e4*4) : z4;
        *(float4*)(sx + r*384 + e4*4) = val;
    }
    __syncthreads();
    int e = threadIdx.x;
    float4 wv = *(const float4*)(w + e*4);
    float cbe = cb[e];
    #pragma unroll 4
    for (int li = 0; li < 16; li++) {
        float acc = cbe;
        acc = fmaf(sx[(li+0)*384 + e], wv.x, acc);
        acc = fmaf(sx[(li+1)*384 + e], wv.y, acc);
        acc = fmaf(sx[(li+2)*384 + e], wv.z, acc);
        acc = fmaf(sx[(li+3)*384 + e], wv.w, acc);
        float sg = 1.f / (1.f + __expf(-acc));
        xo[((size_t)b*L + l0 + li)*DIN + e] = acc * sg;
    }
}

// ---------------- chunked selective scan (2 kernels; lookback fused) --------
__global__ void scan_chunk_local(const float* __restrict__ dt, const float* __restrict__ xi,
                                 const float* __restrict__ proj, const float* __restrict__ A_log,
                                 float* __restrict__ Pc, float* __restrict__ Hc,
                                 int L, int NCH) {
    int b  = blockIdx.x / (DIN/8);
    int ch = blockIdx.x % (DIN/8);
    int chunk = blockIdx.y;
    int e = ch*8 + (threadIdx.x >> 4);
    int n = threadIdx.x & 15;
    float A = -expf(A_log[e*NSz + n]);
    float h = 0.f, P = 1.f;
    int l0 = chunk*64;
    int lend = min(l0 + 64, L);
    size_t base_de = (size_t)b*L*DIN + e;
    size_t base_p  = (size_t)b*L*44 + DTRz + n;
    for (int l = l0; l < lend; l++) {
        float tdt = dt[base_de + (size_t)l*DIN];
        float txi = xi[base_de + (size_t)l*DIN];
        float tB  = proj[base_p + (size_t)l*44];
        float dA = __expf(tdt * A);
        h = fmaf(dA, h, tdt*txi*tB);
        P *= dA;
    }
    size_t idx = ((size_t)(b*NCH + chunk)*DIN + e)*NSz + n;
    Pc[idx] = P;
    Hc[idx] = h;
}

__global__ void scan_chunk_final(const float* __restrict__ dt, const float* __restrict__ xi,
                                 const float* __restrict__ proj, const float* __restrict__ xz,
                                 const float* __restrict__ A_log, const float* __restrict__ Dskip,
                                 const float* __restrict__ Pc, const float* __restrict__ Hc,
                                 float* __restrict__ y, int L, int NCH) {
    int b  = blockIdx.x / (DIN/8);
    int ch = blockIdx.x % (DIN/8);
    int chunk = blockIdx.y;
    int e = ch*8 + (threadIdx.x >> 4);
    int n = threadIdx.x & 15;
    float A  = -expf(A_log[e*NSz + n]);
    float Dk = Dskip[e];
    float h = 0.f;
    {
        size_t idx = ((size_t)b*NCH*DIN + e)*NSz + n;
        size_t step = (size_t)DIN*NSz;
        for (int cc = 0; cc < chunk; cc++) {
            h = fmaf(Pc[idx], h, Hc[idx]);
            idx += step;
        }
    }
    int l0 = chunk*64;
    int lend = min(l0 + 64, L);
    size_t base_de = (size_t)b*L*DIN + e;
    size_t base_p  = (size_t)b*L*44;
    size_t base_z  = (size_t)b*L*(2*DIN) + DIN + e;
    for (int l = l0; l < lend; l++) {
        float tdt = dt[base_de + (size_t)l*DIN];
        float txi = xi[base_de + (size_t)l*DIN];
        float tB  = proj[base_p + (size_t)l*44 + DTRz + n];
        float tC  = proj[base_p + (size_t)l*44 + DTRz + NSz + n];
        float dA = __expf(tdt * A);
        h = fmaf(dA, h, tdt*txi*tB);
        float p = h * tC;
        p += __shfl_xor_sync(0xffffffffu, p, 8);
        p += __shfl_xor_sync(0xffffffffu, p, 4);
        p += __shfl_xor_sync(0xffffffffu, p, 2);
        p += __shfl_xor_sync(0xffffffffu, p, 1);
        if (n == 0) {
            float zv = xz[base_z + (size_t)l*(2*DIN)];
            float sz = zv / (1.f + __expf(-zv));
            y[base_de + (size_t)l*DIN] = (p + Dk*txi) * sz;
        }
    }
}

// ---------------- host ----------------
extern "C" void kernel_launch(void* const* d_in, const int* in_sizes, int n_in,
                              void* d_out, int out_size) {
    const float* x      = (const float*)d_in[0];
    const float* proj_w = (const float*)d_in[1];
    const float* proj_b = (const float*)d_in[2];
    const float* bn_g   = (const float*)d_in[3];
    const float* bn_b   = (const float*)d_in[4];
    const float* bn_mean= (const float*)d_in[5];
    const float* bn_var = (const float*)d_in[6];
    const float* ln_g   = (const float*)d_in[7];
    const float* ln_b   = (const float*)d_in[8];
    const float* Win    = (const float*)d_in[9];
    const float* b_in   = (const float*)d_in[10];
    const float* conv_w = (const float*)d_in[11];
    const float* conv_b = (const float*)d_in[12];
    const float* Wx     = (const float*)d_in[13];
    const float* Wdt    = (const float*)d_in[14];
    const float* bdt    = (const float*)d_in[15];
    const float* A_log  = (const float*)d_in[16];
    const float* Dskip  = (const float*)d_in[17];
    const float* Wout   = (const float*)d_in[18];
    const float* bout   = (const float*)d_in[19];
    float* out = (float*)d_out;

    float *px, *ph, *pxz, *pxi, *pproj, *pdt, *py, *pblk, *pPc, *pHc, *pw2, *pb2;
    cudaGetSymbolAddress((void**)&px,    g_x);
    cudaGetSymbolAddress((void**)&ph,    g_h);
    cudaGetSymbolAddress((void**)&pxz,   g_xz);
    cudaGetSymbolAddress((void**)&pxi,   g_xi);
    cudaGetSymbolAddress((void**)&pproj, g_proj);
    cudaGetSymbolAddress((void**)&pdt,   g_dt);
    cudaGetSymbolAddress((void**)&py,    g_y);
    cudaGetSymbolAddress((void**)&pblk,  g_blk);
    cudaGetSymbolAddress((void**)&pPc,   g_Pc);
    cudaGetSymbolAddress((void**)&pHc,   g_Hc);
    cudaGetSymbolAddress((void**)&pw2,   g_w2);
    cudaGetSymbolAddress((void**)&pb2,   g_b2);

    // ---- stem: fused transpose + BN-fold, then GEMM -> px (B,L,192)
    stem_prep<<<588 + (Dm*CIN + 255)/256, 256>>>(
        x, ph, proj_w, proj_b, bn_g, bn_b, bn_mean, bn_var, pw2, pb2);
    bgemm<64><<<dim3(Dm/64, (BL0+127)/128), 256>>>(
        ph, CIN, pw2, CIN, pb2, px, Dm, BL0, Dm, CIN, 0, 0);

    auto run_block = [&](int i, int L, float* dst, int addC, int pool, cudaStream_t st) {
        int BLc = Bz * L;
        int NCH = (L + 63) / 64;
        int mtiles = (BLc + 127) / 128;

        if (pool) ln_pool<<<BLc/8, 256, 0, st>>>(px, ln_g + i*Dm, ln_b + i*Dm, ph);
        else      ln_row <<<BLc/8, 256, 0, st>>>(px, ln_g + i*Dm, ln_b + i*Dm, ph);

        bgemm<128><<<dim3((2*DIN)/128, mtiles), 256, 0, st>>>(
            ph, Dm, Win + (size_t)i*2*DIN*Dm, Dm,
            b_in + i*2*DIN, pxz, 2*DIN, BLc, 2*DIN, Dm, 0, 0);

        conv_silu2<<<Bz*(L/16), 384, 0, st>>>(pxz, conv_w + i*DIN*KC, conv_b + i*DIN, pxi, L);

        bgemm<64><<<dim3(1, mtiles), 256, 0, st>>>(
            pxi, DIN, Wx + (size_t)i*44*DIN, DIN,
            nullptr, pproj, 44, BLc, 44, DIN, 0, 0);

        bgemm<64><<<dim3(DIN/64, mtiles), 256, 0, st>>>(
            pproj, 44, Wdt + (size_t)i*DIN*DTRz, DTRz,
            bdt + i*DIN, pdt, DIN, BLc, DIN, DTRz, 1, 0);

        dim3 gsc(Bz*(DIN/8), NCH);
        scan_chunk_local<<<gsc, 128, 0, st>>>(pdt, pxi, pproj,
                                       A_log + (size_t)i*DIN*NSz, pPc, pHc, L, NCH);
        scan_chunk_final<<<gsc, 128, 0, st>>>(pdt, pxi, pproj, pxz,
                                       A_log + (size_t)i*DIN*NSz, Dskip + i*DIN,
                                       pPc, pHc, py, L, NCH);

        bgemm<64><<<dim3(Dm/64, mtiles), 256, 0, st>>>(
            py, DIN, Wout + (size_t)i*Dm*DIN, DIN,
            bout + i*Dm, dst, Dm, BLc, Dm, DIN, 0, addC);
    };

    run_block(0, L0z, px, 1, 0, 0);    // x += blk0(x)
    run_block(1, L0z, px, 1, 0, 0);    // x += blk1(x)

    // fork: skip-output transpose runs concurrently with block 2
    cudaStream_t side;
    cudaEvent_t evFork, evJoin;
    cudaStreamCreateWithFlags(&side, cudaStreamNonBlocking);
    cudaEventCreateWithFlags(&evFork, cudaEventDisableTiming);
    cudaEventCreateWithFlags(&evJoin, cudaEventDisableTiming);
    cudaEventRecord(evFork, 0);
    cudaStreamWaitEvent(side, evFork, 0);
    transpose_ld<<<dim3(L0z/32, Dm/32, Bz), dim3(32,8), 0, side>>>(
        px, out + (size_t)Bz*Dm*L1z, L0z);
    cudaEventRecord(evJoin, side);

    // block 2 on pooled input (maxpool fused into ln_pool)
    run_block(2, L1z, pblk, 0, 1, 0);
    transpose_ld<<<dim3((L1z+31)/32, Dm/32, Bz), dim3(32,8)>>>(pblk, out, L1z);

    cudaStreamWaitEvent(0, evJoin, 0);
    // streams/events intentionally not destroyed (kernel_launch is called at
    // most twice; destruction during active capture is the riskier path)
}